// round 11
// baseline (speedup 1.0000x reference)
#include <cuda_runtime.h>
#include <cuda_fp16.h>
#include <math.h>
#include <stdint.h>

// Problem constants (B,T,H,A) = (64, 2048, 1024, 256)
#define BB 64
#define TT 2048
#define HH 1024
#define AA 256
#define BT (BB*TT)          // 131072 rows
#define NCTA (BT/M_CTA)     // 1024 CTAs, 16 per batch
#define CPB2 32             // S-partials per batch (2 halves x 16 CTAs)

#define M_CTA 128
#define KSTEP 32
#define NK (HH/KSTEP)       // 32
#define A_STRIDE 40         // halfs per A row (pad: 80B, conflict-free LDSM)
#define B_STRIDE 264        // halfs per B row (pad: 528B, conflict-free LDSM)
#define A_TILE (M_CTA*A_STRIDE)   // 5120 halfs / stage
#define B_TILE (KSTEP*B_STRIDE)   // 8448 halfs / stage

// ---------------- device scratch (no allocations allowed) ----------------
__device__ float g_S[(size_t)2 * NCTA * HH];   // per-half-chunk weighted sums (8MB)
__device__ float g_m[2 * NCTA];                // per-half-chunk max
__device__ float g_l[2 * NCTA];                // per-half-chunk exp-sum
__device__ __align__(16) __half g_Wh[HH * AA]; // W in fp16 [H][A]

__device__ __forceinline__ uint32_t smem_u32(const void* p) {
    uint32_t a;
    asm("{ .reg .u64 t; cvta.to.shared.u64 t, %1; cvt.u32.u64 %0, t; }" : "=r"(a) : "l"(p));
    return a;
}

// =====================================================================
// K0: convert W [H,A] fp32 -> g_Wh fp16 (rn)
// =====================================================================
__global__ void convert_w_kernel(const float* __restrict__ W)
{
    const int i = (blockIdx.x * 256 + threadIdx.x) * 4;
    const float4 f = *reinterpret_cast<const float4*>(W + i);
    __half2 h0 = __floats2half2_rn(f.x, f.y);
    __half2 h1 = __floats2half2_rn(f.z, f.w);
    *reinterpret_cast<uint2*>(g_Wh + i) =
        make_uint2(*reinterpret_cast<uint32_t*>(&h0), *reinterpret_cast<uint32_t*>(&h1));
}

// =====================================================================
// K1: fp16 mma.m16n8k16 GEMM with FP16 ACCUMULATION chained across each
//     k-step (K=32), flushed into fp32 masters once per k-step.
//     128x256 CTA tile, double-buffered (A via regs+STS, B via cp.async),
//     two syncs per k-step (R3 skeleton). Fused chunked-softmax epilogue.
// 512 threads = 16 warps (4x4); warp tile 32 rows x 64 cols.
// =====================================================================
__global__ __launch_bounds__(512, 1)
void vu_fp16_kernel(const float* __restrict__ x,
                    const float* __restrict__ bo, const float* __restrict__ uo)
{
    extern __shared__ char smem[];
    __half* As = reinterpret_cast<__half*>(smem);                    // [2][A_TILE]
    __half* Bs = reinterpret_cast<__half*>(smem) + 2 * A_TILE;       // [2][B_TILE]
    __shared__ float vu_s[M_CTA];
    __shared__ float redm;

    const int tid  = threadIdx.x;
    const int lane = tid & 31;
    const int warp = tid >> 5;
    const int g    = lane >> 2;           // groupID
    const int tg   = lane & 3;            // thread-in-group
    const int wrow = (warp >> 2) * 32;    // 0,32,64,96
    const int wcol = (warp & 3) * 64;     // 0,64,128,192

    const uint32_t asBase = smem_u32(As);
    const uint32_t bsBase = smem_u32(Bs);

    const size_t row0 = (size_t)blockIdx.x * M_CTA;

    // ---- gmem staging mapping ----
    const int ar = tid >> 2;              // A row 0..127
    const int ak = (tid & 3) * 8;         // A k-sub 0,8,16,24
    const float* aPtr = x + (row0 + ar) * HH + ak;

    const int bk = tid >> 4;              // B k-row 0..31
    const int bn = (tid & 15) * 16;       // B n 0..240
    const __half* bPtr = g_Wh + (size_t)bk * AA + bn;
    const uint32_t bDst = bsBase + (bk * B_STRIDE + bn) * 2;

    float acc[2][8][4];                   // fp32 masters
    #pragma unroll
    for (int mi = 0; mi < 2; mi++)
        #pragma unroll
        for (int ni = 0; ni < 8; ni++)
            #pragma unroll
            for (int c = 0; c < 4; c++) acc[mi][ni][c] = 0.f;

    __half2 aR[4];

    auto ldgA = [&](int k0) {
        const float4 f0 = *reinterpret_cast<const float4*>(aPtr + k0);
        const float4 f1 = *reinterpret_cast<const float4*>(aPtr + k0 + 4);
        aR[0] = __floats2half2_rn(f0.x, f0.y);
        aR[1] = __floats2half2_rn(f0.z, f0.w);
        aR[2] = __floats2half2_rn(f1.x, f1.y);
        aR[3] = __floats2half2_rn(f1.z, f1.w);
    };
    auto stsA = [&](int st) {
        *reinterpret_cast<uint4*>(As + st * A_TILE + ar * A_STRIDE + ak) =
            *reinterpret_cast<uint4*>(aR);
    };
    auto cpB = [&](int st, int k0) {
        const __half* src = bPtr + (size_t)k0 * AA;
        const uint32_t dst = bDst + st * (B_TILE * 2);
        asm volatile("cp.async.cg.shared.global [%0], [%1], 16;"
                     :: "r"(dst), "l"(src) : "memory");
        asm volatile("cp.async.cg.shared.global [%0], [%1], 16;"
                     :: "r"(dst + 16), "l"(src + 8) : "memory");
        asm volatile("cp.async.commit_group;" ::: "memory");
    };

    // fp16-accumulated k-step: 2 subs chained in Dh, then flush to fp32.
    auto compute = [&](int st) {
        const uint32_t aB = asBase + st * (A_TILE * 2);
        const uint32_t bB = bsBase + st * (B_TILE * 2);
        uint32_t Dh[2][8][2];             // fp16x2 accumulators (32 regs)
        #pragma unroll
        for (int sub = 0; sub < 2; sub++) {
            uint32_t a[2][4];
            #pragma unroll
            for (int mi = 0; mi < 2; mi++) {
                const uint32_t addr = aB +
                    ((wrow + mi * 16 + (lane & 15)) * A_STRIDE
                     + sub * 16 + (lane >> 4) * 8) * 2;
                asm volatile("ldmatrix.sync.aligned.m8n8.x4.shared.b16 "
                             "{%0,%1,%2,%3}, [%4];"
                             : "=r"(a[mi][0]), "=r"(a[mi][1]),
                               "=r"(a[mi][2]), "=r"(a[mi][3]) : "r"(addr));
            }
            #pragma unroll
            for (int nb = 0; nb < 4; nb++) {
                uint32_t b0, b1, b2, b3;
                const uint32_t addr = bB +
                    ((sub * 16 + (lane & 15)) * B_STRIDE
                     + wcol + nb * 16 + (lane >> 4) * 8) * 2;
                asm volatile("ldmatrix.sync.aligned.m8n8.x4.trans.shared.b16 "
                             "{%0,%1,%2,%3}, [%4];"
                             : "=r"(b0), "=r"(b1), "=r"(b2), "=r"(b3) : "r"(addr));
                #pragma unroll
                for (int mi = 0; mi < 2; mi++) {
                    if (sub == 0) {
                        asm volatile(
                            "mma.sync.aligned.m16n8k16.row.col.f16.f16.f16.f16 "
                            "{%0,%1},{%2,%3,%4,%5},{%6,%7},{%8,%9};"
                            : "=r"(Dh[mi][nb*2][0]), "=r"(Dh[mi][nb*2][1])
                            : "r"(a[mi][0]), "r"(a[mi][1]), "r"(a[mi][2]), "r"(a[mi][3]),
                              "r"(b0), "r"(b1), "r"(0u), "r"(0u));
                        asm volatile(
                            "mma.sync.aligned.m16n8k16.row.col.f16.f16.f16.f16 "
                            "{%0,%1},{%2,%3,%4,%5},{%6,%7},{%8,%9};"
                            : "=r"(Dh[mi][nb*2+1][0]), "=r"(Dh[mi][nb*2+1][1])
                            : "r"(a[mi][0]), "r"(a[mi][1]), "r"(a[mi][2]), "r"(a[mi][3]),
                              "r"(b2), "r"(b3), "r"(0u), "r"(0u));
                    } else {
                        asm volatile(
                            "mma.sync.aligned.m16n8k16.row.col.f16.f16.f16.f16 "
                            "{%0,%1},{%2,%3,%4,%5},{%6,%7},{%0,%1};"
                            : "+r"(Dh[mi][nb*2][0]), "+r"(Dh[mi][nb*2][1])
                            : "r"(a[mi][0]), "r"(a[mi][1]), "r"(a[mi][2]), "r"(a[mi][3]),
                              "r"(b0), "r"(b1));
                        asm volatile(
                            "mma.sync.aligned.m16n8k16.row.col.f16.f16.f16.f16 "
                            "{%0,%1},{%2,%3,%4,%5},{%6,%7},{%0,%1};"
                            : "+r"(Dh[mi][nb*2+1][0]), "+r"(Dh[mi][nb*2+1][1])
                            : "r"(a[mi][0]), "r"(a[mi][1]), "r"(a[mi][2]), "r"(a[mi][3]),
                              "r"(b2), "r"(b3));
                    }
                }
            }
        }
        // flush fp16 k-step partials into fp32 masters
        #pragma unroll
        for (int mi = 0; mi < 2; mi++)
            #pragma unroll
            for (int ni = 0; ni < 8; ni++) {
                const float2 lo = __half22float2(
                    *reinterpret_cast<__half2*>(&Dh[mi][ni][0]));
                const float2 hi = __half22float2(
                    *reinterpret_cast<__half2*>(&Dh[mi][ni][1]));
                acc[mi][ni][0] += lo.x;
                acc[mi][ni][1] += lo.y;
                acc[mi][ni][2] += hi.x;
                acc[mi][ni][3] += hi.y;
            }
    };

    // ---- prologue: fill stage 0 ----
    ldgA(0);
    cpB(0, 0);
    stsA(0);
    asm volatile("cp.async.wait_group 0;" ::: "memory");
    __syncthreads();

    // ---- main loop: R3 two-sync skeleton ----
    for (int ks = 0; ks < NK; ks++) {
        const int cur = ks & 1;
        const bool more = (ks + 1 < NK);
        if (more) {
            ldgA((ks + 1) * KSTEP);
            cpB(cur ^ 1, (ks + 1) * KSTEP);
        }
        compute(cur);
        __syncthreads();
        if (more) {
            stsA(cur ^ 1);
            asm volatile("cp.async.wait_group 0;" ::: "memory");
            __syncthreads();
        }
    }

    // ---- epilogue 1: vu[row] = sum_a tanh(z + b[a]) * u[a] -> vu_s ----
    if (tid < M_CTA) vu_s[tid] = 0.f;
    __syncthreads();
    #pragma unroll
    for (int mi = 0; mi < 2; mi++) {
        float s0 = 0.f, s1 = 0.f;
        #pragma unroll
        for (int ni = 0; ni < 8; ni++) {
            const int c0 = wcol + ni * 8 + 2 * tg;
            const float b0v = bo[c0], b1v = bo[c0 + 1];
            const float u0v = uo[c0], u1v = uo[c0 + 1];
            s0 += tanhf(acc[mi][ni][0] + b0v) * u0v + tanhf(acc[mi][ni][1] + b1v) * u1v;
            s1 += tanhf(acc[mi][ni][2] + b0v) * u0v + tanhf(acc[mi][ni][3] + b1v) * u1v;
        }
        s0 += __shfl_xor_sync(0xffffffffu, s0, 1);
        s0 += __shfl_xor_sync(0xffffffffu, s0, 2);
        s1 += __shfl_xor_sync(0xffffffffu, s1, 1);
        s1 += __shfl_xor_sync(0xffffffffu, s1, 2);
        if (tg == 0) {
            atomicAdd(&vu_s[wrow + mi * 16 + g],     s0);
            atomicAdd(&vu_s[wrow + mi * 16 + g + 8], s1);
        }
    }
    __syncthreads();

    // ---- epilogue 2: local softmax stats ----
    if (warp == 0) {
        float a = fmaxf(fmaxf(vu_s[lane], vu_s[lane + 32]),
                        fmaxf(vu_s[lane + 64], vu_s[lane + 96]));
        #pragma unroll
        for (int o = 16; o; o >>= 1) a = fmaxf(a, __shfl_xor_sync(0xffffffffu, a, o));
        if (lane == 0) redm = a;
    }
    __syncthreads();
    const float m = redm;
    if (tid < M_CTA) vu_s[tid] = expf(vu_s[tid] - m);   // vu_s now holds weights
    __syncthreads();
    if (warp == 0) {
        float a = vu_s[lane] + vu_s[lane + 32] + vu_s[lane + 64] + vu_s[lane + 96];
        #pragma unroll
        for (int o = 16; o; o >>= 1) a += __shfl_xor_sync(0xffffffffu, a, o);
        if (lane == 0) {
            g_m[2 * blockIdx.x]     = m;  g_l[2 * blockIdx.x]     = a;
            g_m[2 * blockIdx.x + 1] = m;  g_l[2 * blockIdx.x + 1] = 0.f;
        }
    }
    __syncthreads();

    // ---- epilogue 3: S-pass, float4, row-split halves ----
    const int half = warp >> 3;               // 0 or 1
    const int t256 = tid & 255;               // thread index within half
    const float* xr = x + (row0 + half * 64) * HH + t256 * 4;
    const float* wv = vu_s + half * 64;

    float4 s = make_float4(0.f, 0.f, 0.f, 0.f);
    #pragma unroll 8
    for (int r = 0; r < 64; r++) {
        const float w = wv[r];
        const float4 v = *reinterpret_cast<const float4*>(xr + (size_t)r * HH);
        s.x = fmaf(w, v.x, s.x);
        s.y = fmaf(w, v.y, s.y);
        s.z = fmaf(w, v.z, s.z);
        s.w = fmaf(w, v.w, s.w);
    }
    *(reinterpret_cast<float4*>(g_S + ((size_t)(2 * blockIdx.x + half)) * HH) + t256) = s;
}

// =====================================================================
// K2: combine 32 half-chunk partials per batch (exact softmax merge),
//     write out [B, H+1] with ones column. 64 CTAs x 256 threads.
// =====================================================================
__global__ __launch_bounds__(256)
void combine_kernel(float* __restrict__ out)
{
    const int b = blockIdx.x, tid = threadIdx.x;
    const int c0 = b * CPB2;
    __shared__ float sm[CPB2], sl[CPB2];
    if (tid < CPB2) { sm[tid] = g_m[c0 + tid]; sl[tid] = g_l[c0 + tid]; }
    __syncthreads();

    float M = -1e30f;
    #pragma unroll
    for (int c = 0; c < CPB2; c++) M = fmaxf(M, sm[c]);
    float ec[CPB2];
    float L = 0.f;
    #pragma unroll
    for (int c = 0; c < CPB2; c++) {
        ec[c] = expf(sm[c] - M);
        L += ec[c] * sl[c];
    }
    const float inv = 1.f / L;

    for (int h = tid; h < HH; h += 256) {
        float s = 0.f;
        #pragma unroll
        for (int c = 0; c < CPB2; c++)
            s += ec[c] * g_S[(size_t)(c0 + c) * HH + h];
        out[b * (HH + 1) + h] = s * inv;
    }
    if (tid == 0) out[b * (HH + 1) + HH] = 1.0f;
}

// ---------------------------------------------------------------------
extern "C" void kernel_launch(void* const* d_in, const int* in_sizes, int n_in,
                              void* d_out, int out_size)
{
    const float* x  = (const float*)d_in[0];   // [64,2048,1024]
    const float* W  = (const float*)d_in[1];   // [1024,256]
    const float* bo = (const float*)d_in[2];   // [256]
    const float* uo = (const float*)d_in[3];   // [256]
    float* out = (float*)d_out;                // [64,1025]

    const int DSMEM = (2 * A_TILE + 2 * B_TILE) * 2;   // 54272 bytes
    static bool attr_done = false;
    if (!attr_done) {
        cudaFuncSetAttribute(vu_fp16_kernel,
                             cudaFuncAttributeMaxDynamicSharedMemorySize, DSMEM);
        attr_done = true;
    }

    convert_w_kernel<<<(HH * AA) / (256 * 4), 256>>>(W);
    vu_fp16_kernel<<<NCTA, 512, DSMEM>>>(x, bo, uo);
    combine_kernel<<<BB, 256>>>(out);
}

// round 12
// speedup vs baseline: 1.2930x; 1.2930x over previous
#include <cuda_runtime.h>
#include <cuda_fp16.h>
#include <math.h>
#include <stdint.h>

// Problem constants (B,T,H,A) = (64, 2048, 1024, 256)
#define BB 64
#define TT 2048
#define HH 1024
#define AA 256
#define BT (BB*TT)          // 131072 rows
#define NCTA (BT/M_CTA)     // 1024 CTAs, 16 per batch
#define CPB2 32             // S-partials per batch (2 halves x 16 CTAs)

#define M_CTA 128
#define KSTEP 64
#define NK (HH/KSTEP)       // 16
#define A_STRIDE 72         // halfs per A row (64 + 8 pad; conflict-free LDSM)
#define B_STRIDE 264        // halfs per B row (256 + 8 pad; conflict-free LDSM)
#define A_TILE (M_CTA*A_STRIDE)   // 9216 halfs / stage
#define B_TILE (KSTEP*B_STRIDE)   // 16896 halfs / stage

// ---------------- device scratch (no allocations allowed) ----------------
__device__ float g_S[(size_t)2 * NCTA * HH];   // per-half-chunk weighted sums (8MB)
__device__ float g_m[2 * NCTA];                // per-half-chunk max
__device__ float g_l[2 * NCTA];                // per-half-chunk exp-sum
__device__ __align__(16) __half g_Wh[HH * AA]; // W in fp16 [H][A]

__device__ __forceinline__ uint32_t smem_u32(const void* p) {
    uint32_t a;
    asm("{ .reg .u64 t; cvta.to.shared.u64 t, %1; cvt.u32.u64 %0, t; }" : "=r"(a) : "l"(p));
    return a;
}

// =====================================================================
// K0: convert W [H,A] fp32 -> g_Wh fp16 (rn)
// =====================================================================
__global__ void convert_w_kernel(const float* __restrict__ W)
{
    const int i = (blockIdx.x * 256 + threadIdx.x) * 4;
    const float4 f = *reinterpret_cast<const float4*>(W + i);
    __half2 h0 = __floats2half2_rn(f.x, f.y);
    __half2 h1 = __floats2half2_rn(f.z, f.w);
    *reinterpret_cast<uint2*>(g_Wh + i) =
        make_uint2(*reinterpret_cast<uint32_t*>(&h0), *reinterpret_cast<uint32_t*>(&h1));
}

// =====================================================================
// K1: fp16 mma.m16n8k16 GEMM (128x256 CTA tile), KSTEP=64 (4 MMA subs
//     per iteration, HALF the barriers of R10), double-buffered:
//     A via reg-prefetch+STS, B via cp.async. Two syncs per iteration.
//     Fused chunked-softmax epilogue (R10, unchanged).
// 512 threads = 16 warps (4x4); warp tile 32 rows x 64 cols.
// =====================================================================
__global__ __launch_bounds__(512, 1)
void vu_fp16_kernel(const float* __restrict__ x,
                    const float* __restrict__ bo, const float* __restrict__ uo)
{
    extern __shared__ char smem[];
    __half* As = reinterpret_cast<__half*>(smem);                    // [2][A_TILE]
    __half* Bs = reinterpret_cast<__half*>(smem) + 2 * A_TILE;       // [2][B_TILE]
    __shared__ float vu_s[M_CTA];
    __shared__ float redm;

    const int tid  = threadIdx.x;
    const int lane = tid & 31;
    const int warp = tid >> 5;
    const int g    = lane >> 2;           // groupID
    const int tg   = lane & 3;            // thread-in-group
    const int wrow = (warp >> 2) * 32;    // 0,32,64,96
    const int wcol = (warp & 3) * 64;     // 0,64,128,192

    const uint32_t asBase = smem_u32(As);
    const uint32_t bsBase = smem_u32(Bs);

    const size_t row0 = (size_t)blockIdx.x * M_CTA;

    // ---- gmem staging mapping ----
    const int ar = tid >> 2;              // A row 0..127
    const int ak = (tid & 3) * 16;        // A k-sub 0,16,32,48
    const float* aPtr = x + (row0 + ar) * HH + ak;

    const int bk = tid >> 3;              // B k-row 0..63
    const int bn = (tid & 7) * 32;        // B n 0,32,...,224
    const __half* bPtr = g_Wh + (size_t)bk * AA + bn;
    const uint32_t bDst = bsBase + (bk * B_STRIDE + bn) * 2;

    float acc[2][8][4];
    #pragma unroll
    for (int mi = 0; mi < 2; mi++)
        #pragma unroll
        for (int ni = 0; ni < 8; ni++)
            #pragma unroll
            for (int c = 0; c < 4; c++) acc[mi][ni][c] = 0.f;

    __half2 aR[8];

    auto ldgA = [&](int k0) {
        #pragma unroll
        for (int q = 0; q < 4; q++) {
            const float4 f = *reinterpret_cast<const float4*>(aPtr + k0 + q * 4);
            aR[q * 2 + 0] = __floats2half2_rn(f.x, f.y);
            aR[q * 2 + 1] = __floats2half2_rn(f.z, f.w);
        }
    };
    auto stsA = [&](int st) {
        uint4* dst = reinterpret_cast<uint4*>(As + st * A_TILE + ar * A_STRIDE + ak);
        dst[0] = reinterpret_cast<uint4*>(aR)[0];
        dst[1] = reinterpret_cast<uint4*>(aR)[1];
    };
    auto cpB = [&](int st, int k0) {
        const __half* src = bPtr + (size_t)k0 * AA;
        const uint32_t dst = bDst + st * (B_TILE * 2);
        asm volatile("cp.async.cg.shared.global [%0], [%1], 16;"
                     :: "r"(dst), "l"(src) : "memory");
        asm volatile("cp.async.cg.shared.global [%0], [%1], 16;"
                     :: "r"(dst + 16), "l"(src + 8) : "memory");
        asm volatile("cp.async.cg.shared.global [%0], [%1], 16;"
                     :: "r"(dst + 32), "l"(src + 16) : "memory");
        asm volatile("cp.async.cg.shared.global [%0], [%1], 16;"
                     :: "r"(dst + 48), "l"(src + 24) : "memory");
        asm volatile("cp.async.commit_group;" ::: "memory");
    };

    auto compute = [&](int st) {
        const uint32_t aB = asBase + st * (A_TILE * 2);
        const uint32_t bB = bsBase + st * (B_TILE * 2);
        #pragma unroll
        for (int sub = 0; sub < 4; sub++) {
            uint32_t a[2][4];
            #pragma unroll
            for (int mi = 0; mi < 2; mi++) {
                const uint32_t addr = aB +
                    ((wrow + mi * 16 + (lane & 15)) * A_STRIDE
                     + sub * 16 + (lane >> 4) * 8) * 2;
                asm volatile("ldmatrix.sync.aligned.m8n8.x4.shared.b16 "
                             "{%0,%1,%2,%3}, [%4];"
                             : "=r"(a[mi][0]), "=r"(a[mi][1]),
                               "=r"(a[mi][2]), "=r"(a[mi][3]) : "r"(addr));
            }
            #pragma unroll
            for (int nb = 0; nb < 4; nb++) {
                uint32_t b0, b1, b2, b3;
                const uint32_t addr = bB +
                    ((sub * 16 + (lane & 15)) * B_STRIDE
                     + wcol + nb * 16 + (lane >> 4) * 8) * 2;
                asm volatile("ldmatrix.sync.aligned.m8n8.x4.trans.shared.b16 "
                             "{%0,%1,%2,%3}, [%4];"
                             : "=r"(b0), "=r"(b1), "=r"(b2), "=r"(b3) : "r"(addr));
                #pragma unroll
                for (int mi = 0; mi < 2; mi++) {
                    asm volatile(
                        "mma.sync.aligned.m16n8k16.row.col.f32.f16.f16.f32 "
                        "{%0,%1,%2,%3},{%4,%5,%6,%7},{%8,%9},{%0,%1,%2,%3};"
                        : "+f"(acc[mi][nb*2][0]), "+f"(acc[mi][nb*2][1]),
                          "+f"(acc[mi][nb*2][2]), "+f"(acc[mi][nb*2][3])
                        : "r"(a[mi][0]), "r"(a[mi][1]), "r"(a[mi][2]), "r"(a[mi][3]),
                          "r"(b0), "r"(b1));
                    asm volatile(
                        "mma.sync.aligned.m16n8k16.row.col.f32.f16.f16.f32 "
                        "{%0,%1,%2,%3},{%4,%5,%6,%7},{%8,%9},{%0,%1,%2,%3};"
                        : "+f"(acc[mi][nb*2+1][0]), "+f"(acc[mi][nb*2+1][1]),
                          "+f"(acc[mi][nb*2+1][2]), "+f"(acc[mi][nb*2+1][3])
                        : "r"(a[mi][0]), "r"(a[mi][1]), "r"(a[mi][2]), "r"(a[mi][3]),
                          "r"(b2), "r"(b3));
                }
            }
        }
    };

    // ---- prologue: fill stage 0 ----
    ldgA(0);
    cpB(0, 0);
    stsA(0);
    asm volatile("cp.async.wait_group 0;" ::: "memory");
    __syncthreads();

    // ---- main loop: 16 iterations, 2 syncs each ----
    for (int ks = 0; ks < NK; ks++) {
        const int cur = ks & 1;
        const bool more = (ks + 1 < NK);
        if (more) {
            ldgA((ks + 1) * KSTEP);
            cpB(cur ^ 1, (ks + 1) * KSTEP);
        }
        compute(cur);
        __syncthreads();
        if (more) {
            stsA(cur ^ 1);
            asm volatile("cp.async.wait_group 0;" ::: "memory");
            __syncthreads();
        }
    }

    // ---- epilogue 1: vu[row] = sum_a tanh(z + b[a]) * u[a] -> vu_s ----
    if (tid < M_CTA) vu_s[tid] = 0.f;
    __syncthreads();
    #pragma unroll
    for (int mi = 0; mi < 2; mi++) {
        float s0 = 0.f, s1 = 0.f;
        #pragma unroll
        for (int ni = 0; ni < 8; ni++) {
            const int c0 = wcol + ni * 8 + 2 * tg;
            const float b0v = bo[c0], b1v = bo[c0 + 1];
            const float u0v = uo[c0], u1v = uo[c0 + 1];
            s0 += tanhf(acc[mi][ni][0] + b0v) * u0v + tanhf(acc[mi][ni][1] + b1v) * u1v;
            s1 += tanhf(acc[mi][ni][2] + b0v) * u0v + tanhf(acc[mi][ni][3] + b1v) * u1v;
        }
        s0 += __shfl_xor_sync(0xffffffffu, s0, 1);
        s0 += __shfl_xor_sync(0xffffffffu, s0, 2);
        s1 += __shfl_xor_sync(0xffffffffu, s1, 1);
        s1 += __shfl_xor_sync(0xffffffffu, s1, 2);
        if (tg == 0) {
            atomicAdd(&vu_s[wrow + mi * 16 + g],     s0);
            atomicAdd(&vu_s[wrow + mi * 16 + g + 8], s1);
        }
    }
    __syncthreads();

    // ---- epilogue 2: local softmax stats ----
    if (warp == 0) {
        float a = fmaxf(fmaxf(vu_s[lane], vu_s[lane + 32]),
                        fmaxf(vu_s[lane + 64], vu_s[lane + 96]));
        #pragma unroll
        for (int o = 16; o; o >>= 1) a = fmaxf(a, __shfl_xor_sync(0xffffffffu, a, o));
        if (lane == 0) redm = a;
    }
    __syncthreads();
    const float m = redm;
    if (tid < M_CTA) vu_s[tid] = expf(vu_s[tid] - m);   // vu_s now holds weights
    __syncthreads();
    if (warp == 0) {
        float a = vu_s[lane] + vu_s[lane + 32] + vu_s[lane + 64] + vu_s[lane + 96];
        #pragma unroll
        for (int o = 16; o; o >>= 1) a += __shfl_xor_sync(0xffffffffu, a, o);
        if (lane == 0) {
            g_m[2 * blockIdx.x]     = m;  g_l[2 * blockIdx.x]     = a;
            g_m[2 * blockIdx.x + 1] = m;  g_l[2 * blockIdx.x + 1] = 0.f;
        }
    }
    __syncthreads();

    // ---- epilogue 3: S-pass, float4, row-split halves (R10) ----
    const int half = warp >> 3;               // 0 or 1
    const int t256 = tid & 255;               // thread index within half
    const float* xr = x + (row0 + half * 64) * HH + t256 * 4;
    const float* wv = vu_s + half * 64;

    float4 s = make_float4(0.f, 0.f, 0.f, 0.f);
    #pragma unroll 8
    for (int r = 0; r < 64; r++) {
        const float w = wv[r];
        const float4 v = *reinterpret_cast<const float4*>(xr + (size_t)r * HH);
        s.x = fmaf(w, v.x, s.x);
        s.y = fmaf(w, v.y, s.y);
        s.z = fmaf(w, v.z, s.z);
        s.w = fmaf(w, v.w, s.w);
    }
    *(reinterpret_cast<float4*>(g_S + ((size_t)(2 * blockIdx.x + half)) * HH) + t256) = s;
}

// =====================================================================
// K2: combine 32 half-chunk partials per batch (exact softmax merge),
//     write out [B, H+1] with ones column. 64 CTAs x 256 threads.
// =====================================================================
__global__ __launch_bounds__(256)
void combine_kernel(float* __restrict__ out)
{
    const int b = blockIdx.x, tid = threadIdx.x;
    const int c0 = b * CPB2;
    __shared__ float sm[CPB2], sl[CPB2];
    if (tid < CPB2) { sm[tid] = g_m[c0 + tid]; sl[tid] = g_l[c0 + tid]; }
    __syncthreads();

    float M = -1e30f;
    #pragma unroll
    for (int c = 0; c < CPB2; c++) M = fmaxf(M, sm[c]);
    float ec[CPB2];
    float L = 0.f;
    #pragma unroll
    for (int c = 0; c < CPB2; c++) {
        ec[c] = expf(sm[c] - M);
        L += ec[c] * sl[c];
    }
    const float inv = 1.f / L;

    for (int h = tid; h < HH; h += 256) {
        float s = 0.f;
        #pragma unroll
        for (int c = 0; c < CPB2; c++)
            s += ec[c] * g_S[(size_t)(c0 + c) * HH + h];
        out[b * (HH + 1) + h] = s * inv;
    }
    if (tid == 0) out[b * (HH + 1) + HH] = 1.0f;
}

// ---------------------------------------------------------------------
extern "C" void kernel_launch(void* const* d_in, const int* in_sizes, int n_in,
                              void* d_out, int out_size)
{
    const float* x  = (const float*)d_in[0];   // [64,2048,1024]
    const float* W  = (const float*)d_in[1];   // [1024,256]
    const float* bo = (const float*)d_in[2];   // [256]
    const float* uo = (const float*)d_in[3];   // [256]
    float* out = (float*)d_out;                // [64,1025]

    const int DSMEM = 2 * (A_TILE + B_TILE) * 2;   // 104448 bytes
    static bool attr_done = false;
    if (!attr_done) {
        cudaFuncSetAttribute(vu_fp16_kernel,
                             cudaFuncAttributeMaxDynamicSharedMemorySize, DSMEM);
        attr_done = true;
    }

    convert_w_kernel<<<(HH * AA) / (256 * 4), 256>>>(W);
    vu_fp16_kernel<<<NCTA, 512, DSMEM>>>(x, bo, uo);
    combine_kernel<<<BB, 256>>>(out);
}